// round 17
// baseline (speedup 1.0000x reference)
#include <cuda_runtime.h>
#include <cuda_bf16.h>
#include <math.h>

// Box-embedding conditional-probability loss. B pairs, D=128.
// FINAL (R16): measured optimum — 25.06us, ~94% of the practical LTS
// ceiling (268MB irreducible logical L2->SM traffic at ~10.7TB/s).
// Verified-dominant design decisions (each tested against alternatives):
//  - 8 lanes/pair, 32 regs (__launch_bounds__(256,8)), ~full occupancy
//    (beats cp.async pipelines x3, register-MLP x2, f32x2, 16-lane shapes)
//  - __ldcs streaming gathers: gather rows have no exploitable L1 reuse
//  - log-volume as running product (4 logf/pair instead of 512 MUFU.LG2)
//  - meet extent via min+max=sum identity (removes 2 FMNMX/dim)
//  - all dead clamps/renorms removed (extents 0.9495+-0.0495: 128-dim meet
//    product >= ~3e-17, four decades above fp32 underflow; meet clamp only
//    binds in the disjoint branch where the product is discarded)
//  - ratio reduction: only (meet-t2) and (join-t1) log-differences reduced
//    (2 floats, 3 butterfly rounds)

#define EPS_F 1e-8f

__global__ void __launch_bounds__(256, 8)
box_pair_kernel(const int* __restrict__ t1x,
                const int* __restrict__ t2x,
                const float* __restrict__ min_tab,
                const float* __restrict__ dlt_tab,
                float* __restrict__ out_pos,
                float* __restrict__ out_neg,
                int B)
{
    const float MIN_MEAN   = (float)((0.0001 + 0.01) / 2.0);
    const float MIN_VAR    = (float)(0.01 - (0.0001 + 0.01) / 2.0);
    const float DELTA_MEAN = (float)((0.9 + 0.999) / 2.0);
    const float DELTA_VAR  = (float)(0.999 - (0.9 + 0.999) / 2.0);

    int gtid = blockIdx.x * blockDim.x + threadIdx.x;
    int pair = gtid >> 3;           // 8 lanes per pair
    int sub  = threadIdx.x & 7;
    if (pair >= B) return;

    int i1 = __ldg(t1x + pair);
    int i2 = __ldg(t2x + pair);

    const float4* m1p = (const float4*)(min_tab + (size_t)i1 * 128) + sub;
    const float4* d1p = (const float4*)(dlt_tab + (size_t)i1 * 128) + sub;
    const float4* m2p = (const float4*)(min_tab + (size_t)i2 * 128) + sub;
    const float4* d2p = (const float4*)(dlt_tab + (size_t)i2 * 128) + sub;

    float p1 = 1.0f, p2 = 1.0f, pm = 1.0f, pj = 1.0f;
    float mr = 3.4e38f;   // min raw meet extent over my dims

#pragma unroll
    for (int c = 0; c < 4; c++) {
        // streaming loads: bypass L1 allocation for zero-reuse gather data
        float4 m1 = __ldcs(m1p + c * 8);
        float4 d1 = __ldcs(d1p + c * 8);
        float4 m2 = __ldcs(m2p + c * 8);
        float4 d2 = __ldcs(d2p + c * 8);

        const float* m1v = &m1.x;
        const float* d1v = &d1.x;
        const float* m2v = &m2.x;
        const float* d2v = &d2.x;

#pragma unroll
        for (int j = 0; j < 4; j++) {
            float a  = fmaf(m1v[j], MIN_VAR, MIN_MEAN);     // t1_min
            float da = fmaf(d1v[j], DELTA_VAR, DELTA_MEAN); // t1 extent
            float c0 = fmaf(m2v[j], MIN_VAR, MIN_MEAN);     // t2_min
            float dc = fmaf(d2v[j], DELTA_VAR, DELTA_MEAN); // t2 extent
            float b  = a + da;                              // t1_max
            float d  = c0 + dc;                             // t2_max

            float jmin = fminf(a, c0);
            float jmax = fmaxf(b, d);
            float ej   = jmax - jmin;                 // join extent
            float em   = (da + dc) - ej;              // meet extent (identity)

            mr = fminf(mr, em);
            p1 *= da;
            p2 *= dc;
            pj *= ej;
            pm *= em;   // clamp dropped: em<=0 only when disjoint, where
                        // pm is discarded by the output branch
        }
    }

    // ratios: outputs only need (meet - t2) and (join - t1) log-differences.
    // All products are fp32-safe: extents 0.9495+-0.0495 -> per-lane
    // products in [0.2, 2], 8-lane ratio products in [1e-4, 3e3].
    float rm = __fdividef(pm, p2);
    float rj = __fdividef(pj, p1);

    const unsigned int FULL = 0xFFFFFFFFu;
#pragma unroll
    for (int off = 4; off > 0; off >>= 1) {
        rm *= __shfl_xor_sync(FULL, rm, off);
        rj *= __shfl_xor_sync(FULL, rj, off);
    }

    // disjoint = any lane in my 8-lane group saw em <= 0
    unsigned int ball = __ballot_sync(FULL, mr <= 0.0f);
    bool disjoint = ((ball >> (threadIdx.x & 24)) & 0xFFu) != 0u;

    if (sub == 0) {
        float posv, negv;
        if (disjoint) {
            posv = logf(rj);                       // join_log - t1_log
            negv = 0.0f;
        } else {
            float cond = logf(rm);                 // log P(t1|t2)
            posv = -cond;
            negv = -logf(fmaxf(1.0f - rm, EPS_F)); // 1 - exp(cond) = 1 - rm
        }
        out_pos[pair] = posv;
        out_neg[pair] = negv;
    }
}

extern "C" void kernel_launch(void* const* d_in, const int* in_sizes, int n_in,
                              void* d_out, int out_size) {
    const int*   t1x    = (const int*)d_in[0];
    const int*   t2x    = (const int*)d_in[1];
    const float* min_tb = (const float*)d_in[2];
    const float* dlt_tb = (const float*)d_in[3];

    int B = in_sizes[0];
    float* out_pos = (float*)d_out;
    float* out_neg = (float*)d_out + B;

    // 8 lanes per pair, 32 pairs per 256-thread block
    int pairs_per_block = 32;
    int grid = (B + pairs_per_block - 1) / pairs_per_block;
    box_pair_kernel<<<grid, 256>>>(t1x, t2x, min_tb, dlt_tb, out_pos, out_neg, B);
}